// round 13
// baseline (speedup 1.0000x reference)
#include <cuda_runtime.h>

#define Lc 2048
#define Bc 2048
#define NSEG 37          // grid = 37*16 = 592 = 4 blocks x 148 SMs, single balanced wave
#define WUP 4            // warmup steps = exactly one PD-group
#define PD 4             // steps per staged group
#define NBUF 2           // em smem ring buffers (prefetch distance 1 group)
#define MAXSTEP 64       // packed steps per thread (60 used; 64 for stride padding)

typedef unsigned int u32;

// ---------------- device scratch ----------------
__device__ float g_G [NSEG*Bc];
__device__ float g_sc[NSEG*Bc];
__device__ int   g_ct[NSEG*Bc];
__device__ float g_fin[Bc];
__device__ float g_part[16];

__device__ __forceinline__ void cp16(u32 dst, const void* src) {
    asm volatile("cp.async.cg.shared.global [%0], [%1], 16;" :: "r"(dst), "l"(src));
}
__device__ __forceinline__ void cp_commit() { asm volatile("cp.async.commit_group;"); }
__device__ __forceinline__ void cp_wait1()  { asm volatile("cp.async.wait_group 1;"); }

// ---------------- main segmented scan ----------------
// 592 blocks x 128 threads; s = blockIdx>>4, 16 blocks/segment, thread = (chain b, seg s).
__global__ __launch_bounds__(128, 4) void crf_seg(
    const float* __restrict__ em,    const int* __restrict__ tags,
    const int*   __restrict__ qmask, const int* __restrict__ mask,
    const float* __restrict__ startT, const float* __restrict__ endT,
    const float* __restrict__ selfT,  const float* __restrict__ otherT)
{
    __shared__ float shS[49], shO[49], shEO[49];
    __shared__ float4 sEm4[4][NBUF*224];            // per-warp em ring: 2 bufs x (4 steps x 224 floats)
    __shared__ unsigned char sPk[128][MAXSTEP];     // per-thread packed step bytes
    for (int k = threadIdx.x; k < 49; k += 128) {
        float o = otherT[k];
        shS[k] = selfT[k]; shO[k] = o; shEO[k] = __expf(o);
    }
    __syncthreads();

    const int tid  = threadIdx.x;
    const int wid  = tid >> 5, lane = tid & 31;
    const int s    = blockIdx.x >> 4;
    const int b    = ((blockIdx.x & 15) << 7) + tid;
    const int b0   = ((blockIdx.x & 15) << 7) + (wid << 5);   // warp's base chain
    float4* sd = sEm4[wid];
    const float* sEbase = (const float*)sd;
    const int sOfs = 7 * lane;
    // cp.async mapping: thread covers step-row r = lane>>3, chunk c = lane&7 (7 float4s)
    const int cprow = lane >> 3, cpc = (lane & 7) * 7;
    const u32 sdAddr = (u32)__cvta_generic_to_shared(sd);

    // exp(self) matrix in registers (uniform broadcast loads)
    float Es[49];
#pragma unroll
    for (int k = 0; k < 49; k++) Es[k] = __expf(selfT[k]);

    // segment bounds: owned transitions l in (startl, lend]
    const int startl = (s * Lc) / NSEG;                       // 0 for s=0
    const int lend0  = ((s + 1) * Lc) / NSEG;
    const int lend   = (lend0 > Lc - 1) ? (Lc - 1) : lend0;   // only s=36 clamps
    const int lstart = (s == 0) ? 1 : (startl - WUP + 1);
    const int ngrp   = (lend0 - lstart + 1 + PD - 1) / PD;    // 14 (s=0) or 15
    const int nstep  = ngrp * PD;
    const int resetg = (s == 0) ? -1 : 0;                     // warmup = group 0 exactly

    // ---- cp.async prologue: em groups 0 and 1 into slots 0,1 ----
#pragma unroll
    for (int pg = 0; pg < 2; pg++) {
        int l = lstart + pg * PD + cprow; l = (l > Lc - 1) ? (Lc - 1) : l;
        const float4* src = (const float4*)(em + ((size_t)l * Bc + b0) * 7) + cpc;
        u32 dst = sdAddr + (u32)(pg * 224 + cprow * 56 + cpc) * 16u;
#pragma unroll
        for (int i = 0; i < 7; i++) cp16(dst + i * 16u, src + i);
        cp_commit();
    }

    // ---- int pre-pass: pack (tag, mk, cont, scoreable) bytes; trans-score; cnt ----
    float score; int cnt;
    if (s == 0) {
        const float* e0 = em + (size_t)b * 7;
        const int tg0 = tags[b];
        float et = e0[0];
#pragma unroll
        for (int j = 1; j < 7; j++) et = (tg0 == j) ? e0[j] : et;
        score = startT[tg0] + et;
        cnt = mask[b];
    } else {
        score = 0.f; cnt = 0;
    }
    {
        int pb = (lstart - 1) * Bc + b;
        int qprev = qmask[pb], tgprev = tags[pb];
#pragma unroll 4
        for (int i = 0; i < nstep; i++) {
            const int l = lstart + i;
            const int lc = (l > Lc - 1) ? (Lc - 1) : l;
            const int bb = lc * Bc + b;
            const int mkr = mask[bb], q = qmask[bb], tg = tags[bb];
            const int valid = (l <= lend);
            const int mk = valid ? mkr : 0;
            const int cont = (q != qprev) ? 1 : 0;
            const int scb = (l > startl) && mk;               // owned & masked
            if (scb) {
                score += (cont ? shO : shS)[tgprev * 7 + tg];
                cnt++;
            }
            sPk[tid][i] = (unsigned char)(tg | (mk << 3) | (cont << 4) | (scb << 5));
            if (mk) { qprev = q; tgprev = tg; }
        }
    }

    // ---- hot scan loop ----
    float w[7], C;
    if (s == 0) {
        const float* e0 = em + (size_t)b * 7;
        float a[7]; float m = -1e30f;
#pragma unroll
        for (int j = 0; j < 7; j++) { a[j] = startT[j] + e0[j]; m = fmaxf(m, a[j]); }
#pragma unroll
        for (int j = 0; j < 7; j++) w[j] = __expf(a[j] - m);
        C = m;
    } else {
#pragma unroll
        for (int j = 0; j < 7; j++) w[j] = 1.0f;
        C = 0.f;
    }

#pragma unroll 1
    for (int g = 0; g < ngrp; g++) {
        cp_wait1();                     // group g complete (group g+1 may be in flight)
        __syncwarp();

        const int slot = g & 1;
        const float* sE = sEbase + slot * 896;
        const u32 pk4 = *(const u32*)(&sPk[tid][g * 4]);

        // ---- 4 steps from smem ----
#pragma unroll
        for (int k = 0; k < PD; k++) {
            const u32 byte = (pk4 >> (8 * k)) & 0xFFu;
            const bool cont = (byte & 0x10u) != 0u;
            const bool mk   = (byte & 0x08u) != 0u;

            float x[7], e[7];
#pragma unroll
            for (int j = 0; j < 7; j++) x[j] = sE[k * 224 + sOfs + j];
#pragma unroll
            for (int j = 0; j < 7; j++) e[j] = __expf(x[j]);

            float sv[7];
            if (!cont) {
#pragma unroll
                for (int j = 0; j < 7; j++) sv[j] = w[0] * Es[j];
#pragma unroll
                for (int i = 1; i < 7; i++)
#pragma unroll
                    for (int j = 0; j < 7; j++) sv[j] = fmaf(w[i], Es[i * 7 + j], sv[j]);
            } else {
#pragma unroll
                for (int j = 0; j < 7; j++) sv[j] = w[0] * shEO[j];
#pragma unroll
                for (int i = 1; i < 7; i++)
#pragma unroll
                    for (int j = 0; j < 7; j++) sv[j] = fmaf(w[i], shEO[i * 7 + j], sv[j]);
            }
            if (mk) {
#pragma unroll
                for (int j = 0; j < 7; j++) w[j] = sv[j] * e[j];
            }
            if (byte & 0x20u) {                       // owned & masked: em part of score
                score += sE[k * 224 + sOfs + (byte & 7u)];
            }
        }
        __syncwarp();                   // all lanes done reading em slot before refill

        // issue cp.async for em group g+2 into the slot just freed (slot g&1)
        if (g + 2 < ngrp) {
            int l = lstart + (g + 2) * PD + cprow; l = (l > Lc - 1) ? (Lc - 1) : l;
            const float4* src = (const float4*)(em + ((size_t)l * Bc + b0) * 7) + cpc;
            u32 dst = sdAddr + (u32)(slot * 224 + cprow * 56 + cpc) * 16u;
#pragma unroll
            for (int i = 0; i < 7; i++) cp16(dst + i * 16u, src + i);
        }
        cp_commit();                    // commit even when empty: keeps group count aligned

        if (g == resetg) {
            // warmup -> owned boundary: normalize direction, zero log-gain
            float m = w[0];
#pragma unroll
            for (int j = 1; j < 7; j++) m = fmaxf(m, w[j]);
            const float inv = 1.f / m;
#pragma unroll
            for (int j = 0; j < 7; j++) w[j] *= inv;
            C = 0.f;
        } else if (g & 1) {
            // renormalize every 8 steps
            float m = w[0];
#pragma unroll
            for (int j = 1; j < 7; j++) m = fmaxf(m, w[j]);
            C += __logf(m);
            const float inv = 1.f / m;
#pragma unroll
            for (int j = 0; j < 7; j++) w[j] *= inv;
        }
    }

    // finalize segment
    float m = w[0];
#pragma unroll
    for (int j = 1; j < 7; j++) m = fmaxf(m, w[j]);
    g_G [s * Bc + b] = C + __logf(m);
    g_sc[s * Bc + b] = score;
    g_ct[s * Bc + b] = cnt;
    if (s == NSEG - 1) {
        const float inv = 1.f / m;
        float sum = 0.f;
#pragma unroll
        for (int j = 0; j < 7; j++) sum += w[j] * inv * __expf(endT[j]);
        g_fin[b] = __logf(sum);
    }
}

// ---------------- per-chain combine + partial sums ----------------
__global__ void crf_fin(const int* __restrict__ tags,
                        const float* __restrict__ endT) {
    const int b = blockIdx.x * blockDim.x + threadIdx.x;   // 16 x 128 = 2048
    float G = 0.f, sc = 0.f; int ct = 0;
#pragma unroll
    for (int s = 0; s < NSEG; s++) {
        G  += g_G [s * Bc + b];
        sc += g_sc[s * Bc + b];
        ct += g_ct[s * Bc + b];
    }
    const float logZ = G + g_fin[b];
    const int tg_end = tags[(size_t)(ct - 1) * Bc + b];
    const float llh = sc + endT[tg_end] - logZ;

    __shared__ float red[128];
    red[threadIdx.x] = llh;
    __syncthreads();
    for (int off = 64; off > 0; off >>= 1) {
        if (threadIdx.x < off) red[threadIdx.x] += red[threadIdx.x + off];
        __syncthreads();
    }
    if (threadIdx.x == 0) g_part[blockIdx.x] = red[0];
}

__global__ void crf_fin2(float* __restrict__ out) {
    if (threadIdx.x == 0) {
        float s = 0.f;
        for (int k = 0; k < 16; k++) s += g_part[k];
        out[0] = s;
    }
}

// ---------------- launch ----------------
extern "C" void kernel_launch(void* const* d_in, const int* in_sizes, int n_in,
                              void* d_out, int out_size) {
    const float* em     = (const float*)d_in[0];
    const int*   tags   = (const int*)  d_in[1];
    const int*   qmask  = (const int*)  d_in[2];
    const int*   mask   = (const int*)  d_in[3];
    const float* startT = (const float*)d_in[4];
    const float* endT   = (const float*)d_in[5];
    const float* selfT  = (const float*)d_in[6];
    const float* otherT = (const float*)d_in[7];
    float* out = (float*)d_out;

    crf_seg<<<NSEG * 16, 128>>>(em, tags, qmask, mask, startT, endT, selfT, otherT);
    crf_fin<<<16, 128>>>(tags, endT);
    crf_fin2<<<1, 32>>>(out);
}